// round 13
// baseline (speedup 1.0000x reference)
#include <cuda_runtime.h>
#include <cuda_fp16.h>
#include <cstdint>

#define NN   50000
#define MM   25000
#define NNZV 800000
#define F_IN 128
#define HIDC 256
#define F_OUT 128

// ---------------------------------------------------------------------------
// Scratch
// ---------------------------------------------------------------------------
constexpr size_t SZ_XH   = (size_t)NN * F_IN * 2;
constexpr size_t SZ_T1H  = (size_t)MM * F_IN * 2;
constexpr size_t SZ_T2H  = (size_t)NN * F_IN * 2;
constexpr size_t SZ_HH   = (size_t)NN * HIDC * 2;
constexpr size_t SZ_X2H  = (size_t)NN * F_OUT * 2;
constexpr size_t SZ_EH   = (size_t)MM * F_OUT * 2;
constexpr size_t SZ_WT1  = (size_t)HIDC * F_IN * 2;
constexpr size_t SZ_WT2  = (size_t)F_OUT * HIDC * 2;
constexpr size_t SZ_DEGN = (size_t)NN * 4;
constexpr size_t SZ_DEGM = (size_t)MM * 4;
constexpr size_t SZ_OFFN = (size_t)NN * 4;
constexpr size_t SZ_OFFM = (size_t)MM * 4;
constexpr size_t SZ_DINV = (size_t)NN * 4;
constexpr size_t SZ_BINV = (size_t)MM * 4;
constexpr size_t SZ_NE   = (size_t)NNZV * 4;
constexpr size_t SZ_EN   = (size_t)NNZV * 4;
constexpr size_t SZ_RK2  = (size_t)NNZV * 8;   // interleaved (rkN, rkM)
constexpr size_t SZ_BS   = 256 * 4;

constexpr size_t OFF_XH   = 0;
constexpr size_t OFF_T1H  = OFF_XH + SZ_XH;
constexpr size_t OFF_T2H  = OFF_T1H + SZ_T1H;
constexpr size_t OFF_HH   = OFF_T2H + SZ_T2H;
constexpr size_t OFF_X2H  = OFF_HH + SZ_HH;
constexpr size_t OFF_EH   = OFF_X2H + SZ_X2H;
constexpr size_t OFF_WT1  = OFF_EH + SZ_EH;
constexpr size_t OFF_WT2  = OFF_WT1 + SZ_WT1;
constexpr size_t OFF_DEGN = OFF_WT2 + SZ_WT2;
constexpr size_t OFF_DEGM = OFF_DEGN + SZ_DEGN;
constexpr size_t OFF_OFFN = OFF_DEGM + SZ_DEGM;
constexpr size_t OFF_OFFM = OFF_OFFN + SZ_OFFN;
constexpr size_t OFF_DINV = OFF_OFFM + SZ_OFFM;
constexpr size_t OFF_BINV = OFF_DINV + SZ_DINV;
constexpr size_t OFF_NE   = OFF_BINV + SZ_BINV;
constexpr size_t OFF_EN   = OFF_NE + SZ_NE;
constexpr size_t OFF_RK2  = OFF_EN + SZ_EN;
constexpr size_t OFF_BS   = OFF_RK2 + SZ_RK2;
constexpr size_t SCRATCH_TOTAL = OFF_BS + SZ_BS;

__device__ __align__(256) unsigned char g_scratch[SCRATCH_TOTAL];

__device__ __forceinline__ float* scrF(size_t off) {
    return reinterpret_cast<float*>(g_scratch + off);
}
__device__ __forceinline__ int* scrI(size_t off) {
    return reinterpret_cast<int*>(g_scratch + off);
}
__device__ __forceinline__ __half* scrH(size_t off) {
    return reinterpret_cast<__half*>(g_scratch + off);
}

__device__ __forceinline__ uint32_t smem_u32(const void* p) {
    uint32_t a;
    asm("{ .reg .u64 t; cvta.to.shared.u64 t, %1; cvt.u32.u64 %0, t; }"
        : "=r"(a) : "l"(p));
    return a;
}
__device__ __forceinline__ void ldsm_x4(uint32_t& r0, uint32_t& r1,
                                        uint32_t& r2, uint32_t& r3,
                                        uint32_t addr) {
    asm volatile("ldmatrix.sync.aligned.m8n8.x4.shared.b16 {%0,%1,%2,%3}, [%4];"
                 : "=r"(r0), "=r"(r1), "=r"(r2), "=r"(r3) : "r"(addr));
}
__device__ __forceinline__ void mma16816(float* c, const uint32_t* a,
                                         uint32_t b0, uint32_t b1) {
    asm volatile(
        "mma.sync.aligned.m16n8k16.row.col.f32.f16.f16.f32 "
        "{%0,%1,%2,%3}, {%4,%5,%6,%7}, {%8,%9}, {%0,%1,%2,%3};"
        : "+f"(c[0]), "+f"(c[1]), "+f"(c[2]), "+f"(c[3])
        : "r"(a[0]), "r"(a[1]), "r"(a[2]), "r"(a[3]), "r"(b0), "r"(b1));
}

// ---------------------------------------------------------------------------
// Fused prep: zero degrees + x->fp16 + weight transposes (index-partitioned)
// ---------------------------------------------------------------------------
__global__ __launch_bounds__(256) void prep_all_kernel(
    const float4* __restrict__ x,
    const float* __restrict__ W1, const float* __restrict__ W2)
{
    int i = blockIdx.x * blockDim.x + threadIdx.x;

    if (i < NN) scrI(OFF_DEGN)[i] = 0;
    if (i < MM) scrI(OFF_DEGM)[i] = 0;

    if (i < HIDC * F_IN) {
        int n = i / F_IN, k = i % F_IN;
        scrH(OFF_WT1)[i] = __float2half(W1[k * HIDC + n]);
    }
    if (i < F_OUT * HIDC) {
        int n = i / HIDC, k = i % HIDC;
        scrH(OFF_WT2)[i] = __float2half(W2[k * F_OUT + n]);
    }

    if (i < NN * 32) {
        float4 v = __ldg(&x[i]);
        __half2 h01 = __floats2half2_rn(v.x, v.y);
        __half2 h23 = __floats2half2_rn(v.z, v.w);
        uint2 o;
        o.x = *reinterpret_cast<uint32_t*>(&h01);
        o.y = *reinterpret_cast<uint32_t*>(&h23);
        reinterpret_cast<uint2*>(g_scratch + OFF_XH)[i] = o;
    }
}

// ---------------------------------------------------------------------------
// Count degrees + record ranks (interleaved int2), 4 nnz per thread via int4.
// ---------------------------------------------------------------------------
__global__ __launch_bounds__(256) void count_deg_kernel(
    const int4* __restrict__ node_idx4, const int4* __restrict__ edge_idx4)
{
    int t = blockIdx.x * blockDim.x + threadIdx.x;
    if (t >= NNZV / 4) return;
    int* degN = scrI(OFF_DEGN);
    int* degM = scrI(OFF_DEGM);
    int2* rk2 = reinterpret_cast<int2*>(g_scratch + OFF_RK2);

    int4 nv = __ldg(&node_idx4[t]);
    int4 ev = __ldg(&edge_idx4[t]);
    int base = t * 4;
    rk2[base + 0] = make_int2(atomicAdd(&degN[nv.x], 1), atomicAdd(&degM[ev.x], 1));
    rk2[base + 1] = make_int2(atomicAdd(&degN[nv.y], 1), atomicAdd(&degM[ev.y], 1));
    rk2[base + 2] = make_int2(atomicAdd(&degN[nv.z], 1), atomicAdd(&degM[ev.z], 1));
    rk2[base + 3] = make_int2(atomicAdd(&degN[nv.w], 1), atomicAdd(&degM[ev.w], 1));
}

constexpr int SC_ELEMS = 1024;
constexpr int NBLK_N = (NN + SC_ELEMS - 1) / SC_ELEMS;   // 49
constexpr int NBLK_M = (MM + SC_ELEMS - 1) / SC_ELEMS;   // 25
constexpr int NBLK_T = NBLK_N + NBLK_M;                  // 74

__global__ __launch_bounds__(256) void scanA_kernel() {
    int blk = blockIdx.x;
    const int* deg;
    int n, b;
    if (blk < NBLK_N) { deg = scrI(OFF_DEGN); n = NN; b = blk; }
    else              { deg = scrI(OFF_DEGM); n = MM; b = blk - NBLK_N; }
    int tid = threadIdx.x;
    int base = b * SC_ELEMS + tid * 4;
    int s = 0;
    #pragma unroll
    for (int j = 0; j < 4; j++) {
        int i = base + j;
        if (i < n) s += deg[i];
    }
    __shared__ int wsum[8];
    for (int d2 = 16; d2 > 0; d2 >>= 1) s += __shfl_down_sync(0xffffffffu, s, d2);
    if ((tid & 31) == 0) wsum[tid >> 5] = s;
    __syncthreads();
    if (tid < 8) {
        int v = wsum[tid];
        for (int d2 = 4; d2 > 0; d2 >>= 1) v += __shfl_down_sync(0xffu, v, d2);
        if (tid == 0) scrI(OFF_BS)[blk] = v;
    }
}

// scanC with scanB fused: every block redundantly scans the 74 block sums.
// FIX vs R12: bsum init guarded to tid < 128 (was an OOB shared write).
__global__ __launch_bounds__(256) void scanC_kernel() {
    int blk = blockIdx.x;
    const int* deg; int* off; float* inv;
    int n, b;
    if (blk < NBLK_N) {
        deg = scrI(OFF_DEGN); off = scrI(OFF_OFFN);
        inv = scrF(OFF_DINV); n = NN; b = blk;
    } else {
        deg = scrI(OFF_DEGM); off = scrI(OFF_OFFM);
        inv = scrF(OFF_BINV); n = MM; b = blk - NBLK_N;
    }
    int tid = threadIdx.x;

    __shared__ int bsum[128];
    const int* bs = scrI(OFF_BS);
    if (tid < 128) bsum[tid] = (tid < NBLK_T) ? bs[tid] : 0;
    __syncthreads();
    for (int d = 1; d < 128; d <<= 1) {
        int v = (tid >= d && tid < 128) ? bsum[tid - d] : 0;
        __syncthreads();
        if (tid < 128) bsum[tid] += v;
        __syncthreads();
    }
    int blockPre;
    {
        int pre = (blk == 0) ? 0 : bsum[blk - 1];
        if (blk >= NBLK_N) pre -= bsum[NBLK_N - 1];
        blockPre = pre;
    }

    int base = b * SC_ELEMS + tid * 4;
    int d[4];
    int s = 0;
    #pragma unroll
    for (int j = 0; j < 4; j++) {
        int i = base + j;
        d[j] = (i < n) ? deg[i] : 0;
        s += d[j];
    }
    __shared__ int sh[256];
    sh[tid] = s;
    __syncthreads();
    for (int dd = 1; dd < 256; dd <<= 1) {
        int v = (tid >= dd) ? sh[tid - dd] : 0;
        __syncthreads();
        sh[tid] += v;
        __syncthreads();
    }
    int run = blockPre + ((tid == 0) ? 0 : sh[tid - 1]);
    #pragma unroll
    for (int j = 0; j < 4; j++) {
        int i = base + j;
        if (i < n) {
            off[i] = run;
            inv[i] = (d[j] > 0) ? (1.0f / (float)d[j]) : 0.0f;
            run += d[j];
        }
    }
}

// Atomic-free fill, 4 nnz per thread via int4 + int2 rank loads.
__global__ __launch_bounds__(256) void fill_csr_kernel(
    const int4* __restrict__ node_idx4, const int4* __restrict__ edge_idx4)
{
    int t = blockIdx.x * blockDim.x + threadIdx.x;
    if (t >= NNZV / 4) return;
    const int* offN = scrI(OFF_OFFN);
    const int* offM = scrI(OFF_OFFM);
    const int2* rk2 = reinterpret_cast<const int2*>(g_scratch + OFF_RK2);
    int* nodeEdges = scrI(OFF_NE);
    int* edgeNodes = scrI(OFF_EN);

    int4 nv = __ldg(&node_idx4[t]);
    int4 ev = __ldg(&edge_idx4[t]);
    int base = t * 4;
    int2 r0 = __ldg(&rk2[base + 0]);
    int2 r1 = __ldg(&rk2[base + 1]);
    int2 r2 = __ldg(&rk2[base + 2]);
    int2 r3 = __ldg(&rk2[base + 3]);

    nodeEdges[offN[nv.x] + r0.x] = ev.x;
    nodeEdges[offN[nv.y] + r1.x] = ev.y;
    nodeEdges[offN[nv.z] + r2.x] = ev.z;
    nodeEdges[offN[nv.w] + r3.x] = ev.w;
    edgeNodes[offM[ev.x] + r0.y] = nv.x;
    edgeNodes[offM[ev.y] + r1.y] = nv.y;
    edgeNodes[offM[ev.z] + r2.y] = nv.z;
    edgeNodes[offM[ev.w] + r3.y] = nv.w;
}

// ---------------------------------------------------------------------------
// Gather-reduce over fp16 sources (C = 128). One WARP per row, split halves.
// ---------------------------------------------------------------------------
template<bool HAS_BIAS, bool OUT_F, bool OUT_H>
__global__ void gather_h_kernel(size_t srcOff,
                                float* dstFext, size_t dstFOff,
                                size_t dstHOff,
                                size_t offOff, size_t degOff,
                                size_t lstOff, size_t invOff,
                                const float* __restrict__ bias,
                                int nrows)
{
    const uint4* __restrict__ src =
        reinterpret_cast<const uint4*>(g_scratch + srcOff);
    const int* __restrict__ off = scrI(offOff);
    const int* __restrict__ deg = scrI(degOff);
    const int* __restrict__ lst = scrI(lstOff);
    const float* __restrict__ inv = scrF(invOff);

    int row = blockIdx.x * blockDim.y + threadIdx.y;
    if (row >= nrows) return;
    int lane = threadIdx.x;
    int half = lane >> 4;
    int tx   = lane & 15;
    int o = off[row];
    int d = deg[row];

    float a0 = 0.f, a1 = 0.f, a2 = 0.f, a3 = 0.f;
    float a4 = 0.f, a5 = 0.f, a6 = 0.f, a7 = 0.f;

    int j = half;
    for (; j + 14 < d; j += 16) {
        int idx[8];
        #pragma unroll
        for (int q = 0; q < 8; q++) idx[q] = __ldg(&lst[o + j + 2 * q]);
        uint4 v[8];
        #pragma unroll
        for (int q = 0; q < 8; q++) v[q] = __ldg(&src[(size_t)idx[q] * 16 + tx]);
        #pragma unroll
        for (int q = 0; q < 8; q++) {
            float2 f;
            f = __half22float2(*reinterpret_cast<__half2*>(&v[q].x)); a0 += f.x; a1 += f.y;
            f = __half22float2(*reinterpret_cast<__half2*>(&v[q].y)); a2 += f.x; a3 += f.y;
            f = __half22float2(*reinterpret_cast<__half2*>(&v[q].z)); a4 += f.x; a5 += f.y;
            f = __half22float2(*reinterpret_cast<__half2*>(&v[q].w)); a6 += f.x; a7 += f.y;
        }
    }
    if (j + 6 < d) {
        int idx[4];
        #pragma unroll
        for (int q = 0; q < 4; q++) idx[q] = __ldg(&lst[o + j + 2 * q]);
        uint4 v[4];
        #pragma unroll
        for (int q = 0; q < 4; q++) v[q] = __ldg(&src[(size_t)idx[q] * 16 + tx]);
        #pragma unroll
        for (int q = 0; q < 4; q++) {
            float2 f;
            f = __half22float2(*reinterpret_cast<__half2*>(&v[q].x)); a0 += f.x; a1 += f.y;
            f = __half22float2(*reinterpret_cast<__half2*>(&v[q].y)); a2 += f.x; a3 += f.y;
            f = __half22float2(*reinterpret_cast<__half2*>(&v[q].z)); a4 += f.x; a5 += f.y;
            f = __half22float2(*reinterpret_cast<__half2*>(&v[q].w)); a6 += f.x; a7 += f.y;
        }
        j += 8;
    }
    for (; j < d; j += 2) {
        int i0 = __ldg(&lst[o + j]);
        uint4 v0 = __ldg(&src[(size_t)i0 * 16 + tx]);
        float2 f;
        f = __half22float2(*reinterpret_cast<__half2*>(&v0.x)); a0 += f.x; a1 += f.y;
        f = __half22float2(*reinterpret_cast<__half2*>(&v0.y)); a2 += f.x; a3 += f.y;
        f = __half22float2(*reinterpret_cast<__half2*>(&v0.z)); a4 += f.x; a5 += f.y;
        f = __half22float2(*reinterpret_cast<__half2*>(&v0.w)); a6 += f.x; a7 += f.y;
    }

    a0 += __shfl_xor_sync(0xffffffffu, a0, 16);
    a1 += __shfl_xor_sync(0xffffffffu, a1, 16);
    a2 += __shfl_xor_sync(0xffffffffu, a2, 16);
    a3 += __shfl_xor_sync(0xffffffffu, a3, 16);
    a4 += __shfl_xor_sync(0xffffffffu, a4, 16);
    a5 += __shfl_xor_sync(0xffffffffu, a5, 16);
    a6 += __shfl_xor_sync(0xffffffffu, a6, 16);
    a7 += __shfl_xor_sync(0xffffffffu, a7, 16);

    if (half != 0) return;

    float s = inv[row];
    a0 *= s; a1 *= s; a2 *= s; a3 *= s;
    a4 *= s; a5 *= s; a6 *= s; a7 *= s;
    if (HAS_BIAS) {
        const float4* b4 = reinterpret_cast<const float4*>(bias);
        float4 b0 = __ldg(&b4[tx * 2]);
        float4 b1 = __ldg(&b4[tx * 2 + 1]);
        a0 += b0.x; a1 += b0.y; a2 += b0.z; a3 += b0.w;
        a4 += b1.x; a5 += b1.y; a6 += b1.z; a7 += b1.w;
    }
    if (OUT_F) {
        float4* dstF = dstFext
            ? reinterpret_cast<float4*>(dstFext)
            : reinterpret_cast<float4*>(g_scratch + dstFOff);
        dstF[(size_t)row * 32 + tx * 2]     = make_float4(a0, a1, a2, a3);
        dstF[(size_t)row * 32 + tx * 2 + 1] = make_float4(a4, a5, a6, a7);
    }
    if (OUT_H) {
        uint4* dstH = reinterpret_cast<uint4*>(g_scratch + dstHOff);
        __half2 h0 = __floats2half2_rn(a0, a1);
        __half2 h1 = __floats2half2_rn(a2, a3);
        __half2 h2 = __floats2half2_rn(a4, a5);
        __half2 h3 = __floats2half2_rn(a6, a7);
        uint4 ov;
        ov.x = *reinterpret_cast<uint32_t*>(&h0);
        ov.y = *reinterpret_cast<uint32_t*>(&h1);
        ov.z = *reinterpret_cast<uint32_t*>(&h2);
        ov.w = *reinterpret_cast<uint32_t*>(&h3);
        dstH[(size_t)row * 16 + tx] = ov;
    }
}

// ---------------------------------------------------------------------------
// fp16 mma.sync GEMM (unchanged)
// ---------------------------------------------------------------------------
template<int K, int NCOLS, bool HAS_BIAS, bool HAS_ELU>
__global__ __launch_bounds__(256) void gemm_mma_kernel(
    size_t aOff, size_t wtOff, size_t cOff,
    const float* __restrict__ bias, int Mrows)
{
    constexpr int NCHUNK = K / 32;
    constexpr int RS = 40;
    __shared__ __align__(1024) __half As[2][128][RS];
    __shared__ __align__(1024) __half Bs[2][128][RS];

    const __half* __restrict__ A  = scrH(aOff);
    const __half* __restrict__ WT = scrH(wtOff);
    __half* __restrict__ C = scrH(cOff);

    int tid  = threadIdx.x;
    int lane = tid & 31;
    int warp = tid >> 5;
    int warpM = (warp & 3) * 32;
    int warpN = (warp >> 2) * 64;
    int rowBase = blockIdx.y * 128;
    int colBase = blockIdx.x * 128;

    int lrow  = tid >> 2;
    int lcol8 = tid & 3;

    float acc[2][8][4];
    #pragma unroll
    for (int mt = 0; mt < 2; mt++)
        #pragma unroll
        for (int nt = 0; nt < 8; nt++)
            #pragma unroll
            for (int r = 0; r < 4; r++)
                acc[mt][nt][r] = 0.f;

    uint32_t laneRow = lane & 15;
    uint32_t laneK   = (lane >> 4) * 8;
    uint32_t asBase = smem_u32(&As[0][0][0]);
    uint32_t bsBase = smem_u32(&Bs[0][0][0]);
    constexpr uint32_t BUFB = 128 * RS * 2;

    uint4 pa[2], pb[2];
    #pragma unroll
    for (int p = 0; p < 2; p++) {
        int row = p * 64 + lrow;
        int gm = rowBase + row;
        pa[p] = (gm < Mrows)
            ? *(const uint4*)&A[(size_t)gm * K + lcol8 * 8]
            : make_uint4(0u, 0u, 0u, 0u);
        pb[p] = *(const uint4*)&WT[(size_t)(colBase + row) * K + lcol8 * 8];
    }
    #pragma unroll
    for (int p = 0; p < 2; p++) {
        int row = p * 64 + lrow;
        *reinterpret_cast<uint4*>(&As[0][row][lcol8 * 8]) = pa[p];
        *reinterpret_cast<uint4*>(&Bs[0][row][lcol8 * 8]) = pb[p];
    }
    __syncthreads();

    for (int kc = 0; kc < NCHUNK; kc++) {
        int buf = kc & 1;
        bool more = (kc + 1 < NCHUNK);
        if (more) {
            int k0 = (kc + 1) * 32;
            #pragma unroll
            for (int p = 0; p < 2; p++) {
                int row = p * 64 + lrow;
                int gm = rowBase + row;
                pa[p] = (gm < Mrows)
                    ? *(const uint4*)&A[(size_t)gm * K + k0 + lcol8 * 8]
                    : make_uint4(0u, 0u, 0u, 0u);
                pb[p] = *(const uint4*)&WT[(size_t)(colBase + row) * K + k0 + lcol8 * 8];
            }
        }

        uint32_t aBufBase = asBase + (uint32_t)buf * BUFB;
        uint32_t bBufBase = bsBase + (uint32_t)buf * BUFB;
        #pragma unroll
        for (int ks = 0; ks < 2; ks++) {
            uint32_t k0 = ks * 16 + laneK;
            uint32_t af[2][4];
            #pragma unroll
            for (int mt = 0; mt < 2; mt++) {
                uint32_t addr = aBufBase +
                    ((warpM + mt * 16 + laneRow) * RS + k0) * 2;
                ldsm_x4(af[mt][0], af[mt][1], af[mt][2], af[mt][3], addr);
            }
            #pragma unroll
            for (int ng = 0; ng < 4; ng++) {
                uint32_t addr = bBufBase +
                    ((warpN + ng * 16 + laneRow) * RS + k0) * 2;
                uint32_t b0, b1, b2, b3;
                ldsm_x4(b0, b1, b2, b3, addr);
                #pragma unroll
                for (int mt = 0; mt < 2; mt++) {
                    mma16816(acc[mt][ng * 2],     af[mt], b0, b2);
                    mma16816(acc[mt][ng * 2 + 1], af[mt], b1, b3);
                }
            }
        }

        if (more) {
            int nb = buf ^ 1;
            #pragma unroll
            for (int p = 0; p < 2; p++) {
                int row = p * 64 + lrow;
                *reinterpret_cast<uint4*>(&As[nb][row][lcol8 * 8]) = pa[p];
                *reinterpret_cast<uint4*>(&Bs[nb][row][lcol8 * 8]) = pb[p];
            }
        }
        __syncthreads();
    }

    #pragma unroll
    for (int nt = 0; nt < 8; nt++) {
        int c = colBase + warpN + nt * 8 + (lane & 3) * 2;
        float b0 = 0.f, b1 = 0.f;
        if (HAS_BIAS) {
            b0 = __ldg(&bias[c]);
            b1 = __ldg(&bias[c + 1]);
        }
        #pragma unroll
        for (int mt = 0; mt < 2; mt++) {
            int r = rowBase + warpM + mt * 16 + (lane >> 2);
            float v0 = acc[mt][nt][0] + b0;
            float v1 = acc[mt][nt][1] + b1;
            float v2 = acc[mt][nt][2] + b0;
            float v3 = acc[mt][nt][3] + b1;
            if (HAS_ELU) {
                v0 = (v0 > 0.f) ? v0 : expm1f(v0);
                v1 = (v1 > 0.f) ? v1 : expm1f(v1);
                v2 = (v2 > 0.f) ? v2 : expm1f(v2);
                v3 = (v3 > 0.f) ? v3 : expm1f(v3);
            }
            if (r < Mrows) {
                __half2 h = __floats2half2_rn(v0, v1);
                *reinterpret_cast<uint32_t*>(&C[(size_t)r * NCOLS + c]) =
                    *reinterpret_cast<uint32_t*>(&h);
            }
            if (r + 8 < Mrows) {
                __half2 h = __floats2half2_rn(v2, v3);
                *reinterpret_cast<uint32_t*>(&C[(size_t)(r + 8) * NCOLS + c]) =
                    *reinterpret_cast<uint32_t*>(&h);
            }
        }
    }
}

// ---------------------------------------------------------------------------
// Launch: kernel launches ONLY (11 launches).
// ---------------------------------------------------------------------------
extern "C" void kernel_launch(void* const* d_in, const int* in_sizes, int n_in,
                              void* d_out, int out_size)
{
    const float* x        = (const float*)d_in[0];
    const float* W1       = (const float*)d_in[1];
    const float* b1       = (const float*)d_in[2];
    const float* W2       = (const float*)d_in[3];
    const float* b2       = (const float*)d_in[4];
    const int*   node_idx = (const int*)d_in[5];
    const int*   edge_idx = (const int*)d_in[6];

    float* out   = (float*)d_out;
    float* e_out = out + (size_t)NN * F_OUT;

    // ---- prep + CSR build ----
    prep_all_kernel<<<(NN * 32 + 255) / 256, 256>>>((const float4*)x, W1, W2);
    count_deg_kernel<<<(NNZV / 4 + 255) / 256, 256>>>(
        (const int4*)node_idx, (const int4*)edge_idx);
    scanA_kernel<<<NBLK_T, 256>>>();
    scanC_kernel<<<NBLK_T, 256>>>();
    fill_csr_kernel<<<(NNZV / 4 + 255) / 256, 256>>>(
        (const int4*)node_idx, (const int4*)edge_idx);

    dim3 gblk(32, 8);   // one warp per row, 8 rows/block

    // ---- Layer 1 (GEMM commuted past both segment-sums) ----
    gather_h_kernel<false, false, true><<<(MM + 7) / 8, gblk>>>(
        OFF_XH, nullptr, 0, OFF_T1H,
        OFF_OFFM, OFF_DEGM, OFF_EN, OFF_BINV, nullptr, MM);
    gather_h_kernel<false, false, true><<<(NN + 7) / 8, gblk>>>(
        OFF_T1H, nullptr, 0, OFF_T2H,
        OFF_OFFN, OFF_DEGN, OFF_NE, OFF_DINV, nullptr, NN);
    // hh = elu(t2h @ W1 + b1)   fp16 out
    {
        dim3 grid(HIDC / 128, (NN + 127) / 128);
        gemm_mma_kernel<F_IN, HIDC, true, true><<<grid, 256>>>(
            OFF_T2H, OFF_WT1, OFF_HH, b1, NN);
    }

    // ---- Layer 2 ----
    // x2h = hh @ W2   fp16 out
    {
        dim3 grid(F_OUT / 128, (NN + 127) / 128);
        gemm_mma_kernel<HIDC, F_OUT, false, false><<<grid, 256>>>(
            OFF_HH, OFF_WT2, OFF_X2H, nullptr, NN);
    }
    // e_out[m] (fp32, returned) + eh[m] (fp16 copy)
    gather_h_kernel<false, true, true><<<(MM + 7) / 8, gblk>>>(
        OFF_X2H, e_out, 0, OFF_EH,
        OFF_OFFM, OFF_DEGM, OFF_EN, OFF_BINV, nullptr, MM);
    // out[n] = Dinv[n] * sum eh[m] + b2
    gather_h_kernel<true, true, false><<<(NN + 7) / 8, gblk>>>(
        OFF_EH, out, 0, 0,
        OFF_OFFN, OFF_DEGN, OFF_NE, OFF_DINV, b2, NN);
}

// round 16
// speedup vs baseline: 1.0285x; 1.0285x over previous
#include <cuda_runtime.h>
#include <cuda_fp16.h>
#include <cstdint>

#define NN   50000
#define MM   25000
#define NNZV 800000
#define F_IN 128
#define HIDC 256
#define F_OUT 128

// ---------------------------------------------------------------------------
// Scratch
// ---------------------------------------------------------------------------
constexpr size_t SZ_XH   = (size_t)NN * F_IN * 2;
constexpr size_t SZ_T1H  = (size_t)MM * F_IN * 2;
constexpr size_t SZ_T2H  = (size_t)NN * F_IN * 2;
constexpr size_t SZ_HH   = (size_t)NN * HIDC * 2;
constexpr size_t SZ_X2H  = (size_t)NN * F_OUT * 2;
constexpr size_t SZ_EH   = (size_t)MM * F_OUT * 2;
constexpr size_t SZ_WT1  = (size_t)HIDC * F_IN * 2;
constexpr size_t SZ_WT2  = (size_t)F_OUT * HIDC * 2;
constexpr size_t SZ_DEGN = (size_t)NN * 4;
constexpr size_t SZ_DEGM = (size_t)MM * 4;
constexpr size_t SZ_OFFN = (size_t)NN * 4;
constexpr size_t SZ_OFFM = (size_t)MM * 4;
constexpr size_t SZ_DINV = (size_t)NN * 4;
constexpr size_t SZ_BINV = (size_t)MM * 4;
constexpr size_t SZ_NE   = (size_t)NNZV * 4;
constexpr size_t SZ_EN   = (size_t)NNZV * 4;
constexpr size_t SZ_RK   = (size_t)NNZV * 4;   // packed (rkN | rkM<<16)
constexpr size_t SZ_BS   = 256 * 4;

constexpr size_t OFF_XH   = 0;
constexpr size_t OFF_T1H  = OFF_XH + SZ_XH;
constexpr size_t OFF_T2H  = OFF_T1H + SZ_T1H;
constexpr size_t OFF_HH   = OFF_T2H + SZ_T2H;
constexpr size_t OFF_X2H  = OFF_HH + SZ_HH;
constexpr size_t OFF_EH   = OFF_X2H + SZ_X2H;
constexpr size_t OFF_WT1  = OFF_EH + SZ_EH;
constexpr size_t OFF_WT2  = OFF_WT1 + SZ_WT1;
constexpr size_t OFF_DEGN = OFF_WT2 + SZ_WT2;
constexpr size_t OFF_DEGM = OFF_DEGN + SZ_DEGN;
constexpr size_t OFF_OFFN = OFF_DEGM + SZ_DEGM;
constexpr size_t OFF_OFFM = OFF_OFFN + SZ_OFFN;
constexpr size_t OFF_DINV = OFF_OFFM + SZ_OFFM;
constexpr size_t OFF_BINV = OFF_DINV + SZ_DINV;
constexpr size_t OFF_NE   = OFF_BINV + SZ_BINV;
constexpr size_t OFF_EN   = OFF_NE + SZ_NE;
constexpr size_t OFF_RK   = OFF_EN + SZ_EN;
constexpr size_t OFF_BS   = OFF_RK + SZ_RK;
constexpr size_t SCRATCH_TOTAL = OFF_BS + SZ_BS;

__device__ __align__(256) unsigned char g_scratch[SCRATCH_TOTAL];

__device__ __forceinline__ float* scrF(size_t off) {
    return reinterpret_cast<float*>(g_scratch + off);
}
__device__ __forceinline__ int* scrI(size_t off) {
    return reinterpret_cast<int*>(g_scratch + off);
}
__device__ __forceinline__ __half* scrH(size_t off) {
    return reinterpret_cast<__half*>(g_scratch + off);
}

__device__ __forceinline__ uint32_t smem_u32(const void* p) {
    uint32_t a;
    asm("{ .reg .u64 t; cvta.to.shared.u64 t, %1; cvt.u32.u64 %0, t; }"
        : "=r"(a) : "l"(p));
    return a;
}
__device__ __forceinline__ void ldsm_x4(uint32_t& r0, uint32_t& r1,
                                        uint32_t& r2, uint32_t& r3,
                                        uint32_t addr) {
    asm volatile("ldmatrix.sync.aligned.m8n8.x4.shared.b16 {%0,%1,%2,%3}, [%4];"
                 : "=r"(r0), "=r"(r1), "=r"(r2), "=r"(r3) : "r"(addr));
}
__device__ __forceinline__ void mma16816(float* c, const uint32_t* a,
                                         uint32_t b0, uint32_t b1) {
    asm volatile(
        "mma.sync.aligned.m16n8k16.row.col.f32.f16.f16.f32 "
        "{%0,%1,%2,%3}, {%4,%5,%6,%7}, {%8,%9}, {%0,%1,%2,%3};"
        : "+f"(c[0]), "+f"(c[1]), "+f"(c[2]), "+f"(c[3])
        : "r"(a[0]), "r"(a[1]), "r"(a[2]), "r"(a[3]), "r"(b0), "r"(b1));
}

// ---------------------------------------------------------------------------
// Fused prep: zero degrees + x->fp16 + weight transposes
// ---------------------------------------------------------------------------
__global__ __launch_bounds__(256) void prep_all_kernel(
    const float4* __restrict__ x,
    const float* __restrict__ W1, const float* __restrict__ W2)
{
    int i = blockIdx.x * blockDim.x + threadIdx.x;

    if (i < NN) scrI(OFF_DEGN)[i] = 0;
    if (i < MM) scrI(OFF_DEGM)[i] = 0;

    if (i < HIDC * F_IN) {
        int n = i / F_IN, k = i % F_IN;
        scrH(OFF_WT1)[i] = __float2half(W1[k * HIDC + n]);
    }
    if (i < F_OUT * HIDC) {
        int n = i / HIDC, k = i % HIDC;
        scrH(OFF_WT2)[i] = __float2half(W2[k * F_OUT + n]);
    }

    if (i < NN * 32) {
        float4 v = __ldg(&x[i]);
        __half2 h01 = __floats2half2_rn(v.x, v.y);
        __half2 h23 = __floats2half2_rn(v.z, v.w);
        uint2 o;
        o.x = *reinterpret_cast<uint32_t*>(&h01);
        o.y = *reinterpret_cast<uint32_t*>(&h23);
        reinterpret_cast<uint2*>(g_scratch + OFF_XH)[i] = o;
    }
}

// ---------------------------------------------------------------------------
// Count degrees + record ranks packed (rkN | rkM<<16). 1 nnz/thread.
// ---------------------------------------------------------------------------
__global__ __launch_bounds__(256) void count_deg_kernel(
    const int* __restrict__ node_idx, const int* __restrict__ edge_idx)
{
    int* degN = scrI(OFF_DEGN);
    int* degM = scrI(OFF_DEGM);
    uint32_t* rk = reinterpret_cast<uint32_t*>(g_scratch + OFF_RK);
    int stride = gridDim.x * blockDim.x;
    for (int i = blockIdx.x * blockDim.x + threadIdx.x; i < NNZV; i += stride) {
        uint32_t rn = (uint32_t)atomicAdd(&degN[node_idx[i]], 1);
        uint32_t rm = (uint32_t)atomicAdd(&degM[edge_idx[i]], 1);
        rk[i] = rn | (rm << 16);
    }
}

constexpr int SC_ELEMS = 1024;
constexpr int NBLK_N = (NN + SC_ELEMS - 1) / SC_ELEMS;   // 49
constexpr int NBLK_M = (MM + SC_ELEMS - 1) / SC_ELEMS;   // 25
constexpr int NBLK_T = NBLK_N + NBLK_M;                  // 74

__global__ __launch_bounds__(256) void scanA_kernel() {
    int blk = blockIdx.x;
    const int* deg;
    int n, b;
    if (blk < NBLK_N) { deg = scrI(OFF_DEGN); n = NN; b = blk; }
    else              { deg = scrI(OFF_DEGM); n = MM; b = blk - NBLK_N; }
    int tid = threadIdx.x;
    int base = b * SC_ELEMS + tid * 4;
    int s = 0;
    #pragma unroll
    for (int j = 0; j < 4; j++) {
        int i = base + j;
        if (i < n) s += deg[i];
    }
    __shared__ int wsum[8];
    for (int d2 = 16; d2 > 0; d2 >>= 1) s += __shfl_down_sync(0xffffffffu, s, d2);
    if ((tid & 31) == 0) wsum[tid >> 5] = s;
    __syncthreads();
    if (tid < 8) {
        int v = wsum[tid];
        for (int d2 = 4; d2 > 0; d2 >>= 1) v += __shfl_down_sync(0xffu, v, d2);
        if (tid == 0) scrI(OFF_BS)[blk] = v;
    }
}

// scanC with scanB fused (bsum init guarded to tid < 128).
__global__ __launch_bounds__(256) void scanC_kernel() {
    int blk = blockIdx.x;
    const int* deg; int* off; float* inv;
    int n, b;
    if (blk < NBLK_N) {
        deg = scrI(OFF_DEGN); off = scrI(OFF_OFFN);
        inv = scrF(OFF_DINV); n = NN; b = blk;
    } else {
        deg = scrI(OFF_DEGM); off = scrI(OFF_OFFM);
        inv = scrF(OFF_BINV); n = MM; b = blk - NBLK_N;
    }
    int tid = threadIdx.x;

    __shared__ int bsum[128];
    const int* bs = scrI(OFF_BS);
    if (tid < 128) bsum[tid] = (tid < NBLK_T) ? bs[tid] : 0;
    __syncthreads();
    for (int d = 1; d < 128; d <<= 1) {
        int v = (tid >= d && tid < 128) ? bsum[tid - d] : 0;
        __syncthreads();
        if (tid < 128) bsum[tid] += v;
        __syncthreads();
    }
    int blockPre;
    {
        int pre = (blk == 0) ? 0 : bsum[blk - 1];
        if (blk >= NBLK_N) pre -= bsum[NBLK_N - 1];
        blockPre = pre;
    }

    int base = b * SC_ELEMS + tid * 4;
    int d[4];
    int s = 0;
    #pragma unroll
    for (int j = 0; j < 4; j++) {
        int i = base + j;
        d[j] = (i < n) ? deg[i] : 0;
        s += d[j];
    }
    __shared__ int sh[256];
    sh[tid] = s;
    __syncthreads();
    for (int dd = 1; dd < 256; dd <<= 1) {
        int v = (tid >= dd) ? sh[tid - dd] : 0;
        __syncthreads();
        sh[tid] += v;
        __syncthreads();
    }
    int run = blockPre + ((tid == 0) ? 0 : sh[tid - 1]);
    #pragma unroll
    for (int j = 0; j < 4; j++) {
        int i = base + j;
        if (i < n) {
            off[i] = run;
            inv[i] = (d[j] > 0) ? (1.0f / (float)d[j]) : 0.0f;
            run += d[j];
        }
    }
}

// Atomic-free fill, packed ranks, 1 nnz/thread.
__global__ __launch_bounds__(256) void fill_csr_kernel(
    const int* __restrict__ node_idx, const int* __restrict__ edge_idx)
{
    const int* offN = scrI(OFF_OFFN);
    const int* offM = scrI(OFF_OFFM);
    const uint32_t* rk = reinterpret_cast<const uint32_t*>(g_scratch + OFF_RK);
    int* nodeEdges = scrI(OFF_NE);
    int* edgeNodes = scrI(OFF_EN);
    int stride = gridDim.x * blockDim.x;
    for (int i = blockIdx.x * blockDim.x + threadIdx.x; i < NNZV; i += stride) {
        int n = node_idx[i];
        int m = edge_idx[i];
        uint32_t r = rk[i];
        nodeEdges[offN[n] + (int)(r & 0xffffu)] = m;
        edgeNodes[offM[m] + (int)(r >> 16)] = n;
    }
}

// ---------------------------------------------------------------------------
// Gather-reduce over fp16 sources (C = 128). One WARP per row, split halves.
// ---------------------------------------------------------------------------
template<bool HAS_BIAS, bool OUT_F, bool OUT_H>
__global__ void gather_h_kernel(size_t srcOff,
                                float* dstFext, size_t dstFOff,
                                size_t dstHOff,
                                size_t offOff, size_t degOff,
                                size_t lstOff, size_t invOff,
                                const float* __restrict__ bias,
                                int nrows)
{
    const uint4* __restrict__ src =
        reinterpret_cast<const uint4*>(g_scratch + srcOff);
    const int* __restrict__ off = scrI(offOff);
    const int* __restrict__ deg = scrI(degOff);
    const int* __restrict__ lst = scrI(lstOff);
    const float* __restrict__ inv = scrF(invOff);

    int row = blockIdx.x * blockDim.y + threadIdx.y;
    if (row >= nrows) return;
    int lane = threadIdx.x;
    int half = lane >> 4;
    int tx   = lane & 15;
    int o = off[row];
    int d = deg[row];

    float a0 = 0.f, a1 = 0.f, a2 = 0.f, a3 = 0.f;
    float a4 = 0.f, a5 = 0.f, a6 = 0.f, a7 = 0.f;

    int j = half;
    for (; j + 14 < d; j += 16) {
        int idx[8];
        #pragma unroll
        for (int q = 0; q < 8; q++) idx[q] = __ldg(&lst[o + j + 2 * q]);
        uint4 v[8];
        #pragma unroll
        for (int q = 0; q < 8; q++) v[q] = __ldg(&src[(size_t)idx[q] * 16 + tx]);
        #pragma unroll
        for (int q = 0; q < 8; q++) {
            float2 f;
            f = __half22float2(*reinterpret_cast<__half2*>(&v[q].x)); a0 += f.x; a1 += f.y;
            f = __half22float2(*reinterpret_cast<__half2*>(&v[q].y)); a2 += f.x; a3 += f.y;
            f = __half22float2(*reinterpret_cast<__half2*>(&v[q].z)); a4 += f.x; a5 += f.y;
            f = __half22float2(*reinterpret_cast<__half2*>(&v[q].w)); a6 += f.x; a7 += f.y;
        }
    }
    if (j + 6 < d) {
        int idx[4];
        #pragma unroll
        for (int q = 0; q < 4; q++) idx[q] = __ldg(&lst[o + j + 2 * q]);
        uint4 v[4];
        #pragma unroll
        for (int q = 0; q < 4; q++) v[q] = __ldg(&src[(size_t)idx[q] * 16 + tx]);
        #pragma unroll
        for (int q = 0; q < 4; q++) {
            float2 f;
            f = __half22float2(*reinterpret_cast<__half2*>(&v[q].x)); a0 += f.x; a1 += f.y;
            f = __half22float2(*reinterpret_cast<__half2*>(&v[q].y)); a2 += f.x; a3 += f.y;
            f = __half22float2(*reinterpret_cast<__half2*>(&v[q].z)); a4 += f.x; a5 += f.y;
            f = __half22float2(*reinterpret_cast<__half2*>(&v[q].w)); a6 += f.x; a7 += f.y;
        }
        j += 8;
    }
    for (; j < d; j += 2) {
        int i0 = __ldg(&lst[o + j]);
        uint4 v0 = __ldg(&src[(size_t)i0 * 16 + tx]);
        float2 f;
        f = __half22float2(*reinterpret_cast<__half2*>(&v0.x)); a0 += f.x; a1 += f.y;
        f = __half22float2(*reinterpret_cast<__half2*>(&v0.y)); a2 += f.x; a3 += f.y;
        f = __half22float2(*reinterpret_cast<__half2*>(&v0.z)); a4 += f.x; a5 += f.y;
        f = __half22float2(*reinterpret_cast<__half2*>(&v0.w)); a6 += f.x; a7 += f.y;
    }

    a0 += __shfl_xor_sync(0xffffffffu, a0, 16);
    a1 += __shfl_xor_sync(0xffffffffu, a1, 16);
    a2 += __shfl_xor_sync(0xffffffffu, a2, 16);
    a3 += __shfl_xor_sync(0xffffffffu, a3, 16);
    a4 += __shfl_xor_sync(0xffffffffu, a4, 16);
    a5 += __shfl_xor_sync(0xffffffffu, a5, 16);
    a6 += __shfl_xor_sync(0xffffffffu, a6, 16);
    a7 += __shfl_xor_sync(0xffffffffu, a7, 16);

    if (half != 0) return;

    float s = inv[row];
    a0 *= s; a1 *= s; a2 *= s; a3 *= s;
    a4 *= s; a5 *= s; a6 *= s; a7 *= s;
    if (HAS_BIAS) {
        const float4* b4 = reinterpret_cast<const float4*>(bias);
        float4 b0 = __ldg(&b4[tx * 2]);
        float4 b1 = __ldg(&b4[tx * 2 + 1]);
        a0 += b0.x; a1 += b0.y; a2 += b0.z; a3 += b0.w;
        a4 += b1.x; a5 += b1.y; a6 += b1.z; a7 += b1.w;
    }
    if (OUT_F) {
        float4* dstF = dstFext
            ? reinterpret_cast<float4*>(dstFext)
            : reinterpret_cast<float4*>(g_scratch + dstFOff);
        dstF[(size_t)row * 32 + tx * 2]     = make_float4(a0, a1, a2, a3);
        dstF[(size_t)row * 32 + tx * 2 + 1] = make_float4(a4, a5, a6, a7);
    }
    if (OUT_H) {
        uint4* dstH = reinterpret_cast<uint4*>(g_scratch + dstHOff);
        __half2 h0 = __floats2half2_rn(a0, a1);
        __half2 h1 = __floats2half2_rn(a2, a3);
        __half2 h2 = __floats2half2_rn(a4, a5);
        __half2 h3 = __floats2half2_rn(a6, a7);
        uint4 ov;
        ov.x = *reinterpret_cast<uint32_t*>(&h0);
        ov.y = *reinterpret_cast<uint32_t*>(&h1);
        ov.z = *reinterpret_cast<uint32_t*>(&h2);
        ov.w = *reinterpret_cast<uint32_t*>(&h3);
        dstH[(size_t)row * 16 + tx] = ov;
    }
}

// ---------------------------------------------------------------------------
// fp16 mma.sync GEMM (validated)
// ---------------------------------------------------------------------------
template<int K, int NCOLS, bool HAS_BIAS, bool HAS_ELU>
__global__ __launch_bounds__(256) void gemm_mma_kernel(
    size_t aOff, size_t wtOff, size_t cOff,
    const float* __restrict__ bias, int Mrows)
{
    constexpr int NCHUNK = K / 32;
    constexpr int RS = 40;
    __shared__ __align__(1024) __half As[2][128][RS];
    __shared__ __align__(1024) __half Bs[2][128][RS];

    const __half* __restrict__ A  = scrH(aOff);
    const __half* __restrict__ WT = scrH(wtOff);
    __half* __restrict__ C = scrH(cOff);

    int tid  = threadIdx.x;
    int lane = tid & 31;
    int warp = tid >> 5;
    int warpM = (warp & 3) * 32;
    int warpN = (warp >> 2) * 64;
    int rowBase = blockIdx.y * 128;
    int colBase = blockIdx.x * 128;

    int lrow  = tid >> 2;
    int lcol8 = tid & 3;

    float acc[2][8][4];
    #pragma unroll
    for (int mt = 0; mt < 2; mt++)
        #pragma unroll
        for (int nt = 0; nt < 8; nt++)
            #pragma unroll
            for (int r = 0; r < 4; r++)
                acc[mt][nt][r] = 0.f;

    uint32_t laneRow = lane & 15;
    uint32_t laneK   = (lane >> 4) * 8;
    uint32_t asBase = smem_u32(&As[0][0][0]);
    uint32_t bsBase = smem_u32(&Bs[0][0][0]);
    constexpr uint32_t BUFB = 128 * RS * 2;

    uint4 pa[2], pb[2];
    #pragma unroll
    for (int p = 0; p < 2; p++) {
        int row = p * 64 + lrow;
        int gm = rowBase + row;
        pa[p] = (gm < Mrows)
            ? *(const uint4*)&A[(size_t)gm * K + lcol8 * 8]
            : make_uint4(0u, 0u, 0u, 0u);
        pb[p] = *(const uint4*)&WT[(size_t)(colBase + row) * K + lcol8 * 8];
    }
    #pragma unroll
    for (int p = 0; p < 2; p++) {
        int row = p * 64 + lrow;
        *reinterpret_cast<uint4*>(&As[0][row][lcol8 * 8]) = pa[p];
        *reinterpret_cast<uint4*>(&Bs[0][row][lcol8 * 8]) = pb[p];
    }
    __syncthreads();

    for (int kc = 0; kc < NCHUNK; kc++) {
        int buf = kc & 1;
        bool more = (kc + 1 < NCHUNK);
        if (more) {
            int k0 = (kc + 1) * 32;
            #pragma unroll
            for (int p = 0; p < 2; p++) {
                int row = p * 64 + lrow;
                int gm = rowBase + row;
                pa[p] = (gm < Mrows)
                    ? *(const uint4*)&A[(size_t)gm * K + k0 + lcol8 * 8]
                    : make_uint4(0u, 0u, 0u, 0u);
                pb[p] = *(const uint4*)&WT[(size_t)(colBase + row) * K + k0 + lcol8 * 8];
            }
        }

        uint32_t aBufBase = asBase + (uint32_t)buf * BUFB;
        uint32_t bBufBase = bsBase + (uint32_t)buf * BUFB;
        #pragma unroll
        for (int ks = 0; ks < 2; ks++) {
            uint32_t k0 = ks * 16 + laneK;
            uint32_t af[2][4];
            #pragma unroll
            for (int mt = 0; mt < 2; mt++) {
                uint32_t addr = aBufBase +
                    ((warpM + mt * 16 + laneRow) * RS + k0) * 2;
                ldsm_x4(af[mt][0], af[mt][1], af[mt][2], af[mt][3], addr);
            }
            #pragma unroll
            for (int ng = 0; ng < 4; ng++) {
                uint32_t addr = bBufBase +
                    ((warpN + ng * 16 + laneRow) * RS + k0) * 2;
                uint32_t b0, b1, b2, b3;
                ldsm_x4(b0, b1, b2, b3, addr);
                #pragma unroll
                for (int mt = 0; mt < 2; mt++) {
                    mma16816(acc[mt][ng * 2],     af[mt], b0, b2);
                    mma16816(acc[mt][ng * 2 + 1], af[mt], b1, b3);
                }
            }
        }

        if (more) {
            int nb = buf ^ 1;
            #pragma unroll
            for (int p = 0; p < 2; p++) {
                int row = p * 64 + lrow;
                *reinterpret_cast<uint4*>(&As[nb][row][lcol8 * 8]) = pa[p];
                *reinterpret_cast<uint4*>(&Bs[nb][row][lcol8 * 8]) = pb[p];
            }
        }
        __syncthreads();
    }

    #pragma unroll
    for (int nt = 0; nt < 8; nt++) {
        int c = colBase + warpN + nt * 8 + (lane & 3) * 2;
        float b0 = 0.f, b1 = 0.f;
        if (HAS_BIAS) {
            b0 = __ldg(&bias[c]);
            b1 = __ldg(&bias[c + 1]);
        }
        #pragma unroll
        for (int mt = 0; mt < 2; mt++) {
            int r = rowBase + warpM + mt * 16 + (lane >> 2);
            float v0 = acc[mt][nt][0] + b0;
            float v1 = acc[mt][nt][1] + b1;
            float v2 = acc[mt][nt][2] + b0;
            float v3 = acc[mt][nt][3] + b1;
            if (HAS_ELU) {
                v0 = (v0 > 0.f) ? v0 : expm1f(v0);
                v1 = (v1 > 0.f) ? v1 : expm1f(v1);
                v2 = (v2 > 0.f) ? v2 : expm1f(v2);
                v3 = (v3 > 0.f) ? v3 : expm1f(v3);
            }
            if (r < Mrows) {
                __half2 h = __floats2half2_rn(v0, v1);
                *reinterpret_cast<uint32_t*>(&C[(size_t)r * NCOLS + c]) =
                    *reinterpret_cast<uint32_t*>(&h);
            }
            if (r + 8 < Mrows) {
                __half2 h = __floats2half2_rn(v2, v3);
                *reinterpret_cast<uint32_t*>(&C[(size_t)(r + 8) * NCOLS + c]) =
                    *reinterpret_cast<uint32_t*>(&h);
            }
        }
    }
}

// ---------------------------------------------------------------------------
// Launch: kernel launches ONLY (11 launches).
// ---------------------------------------------------------------------------
extern "C" void kernel_launch(void* const* d_in, const int* in_sizes, int n_in,
                              void* d_out, int out_size)
{
    const float* x        = (const float*)d_in[0];
    const float* W1       = (const float*)d_in[1];
    const float* b1       = (const float*)d_in[2];
    const float* W2       = (const float*)d_in[3];
    const float* b2       = (const float*)d_in[4];
    const int*   node_idx = (const int*)d_in[5];
    const int*   edge_idx = (const int*)d_in[6];

    float* out   = (float*)d_out;
    float* e_out = out + (size_t)NN * F_OUT;

    // ---- prep + CSR build ----
    prep_all_kernel<<<(NN * 32 + 255) / 256, 256>>>((const float4*)x, W1, W2);
    count_deg_kernel<<<2048, 256>>>(node_idx, edge_idx);
    scanA_kernel<<<NBLK_T, 256>>>();
    scanC_kernel<<<NBLK_T, 256>>>();
    fill_csr_kernel<<<2048, 256>>>(node_idx, edge_idx);

    dim3 gblk(32, 8);   // one warp per row, 8 rows/block

    // ---- Layer 1 (GEMM commuted past both segment-sums) ----
    gather_h_kernel<false, false, true><<<(MM + 7) / 8, gblk>>>(
        OFF_XH, nullptr, 0, OFF_T1H,
        OFF_OFFM, OFF_DEGM, OFF_EN, OFF_BINV, nullptr, MM);
    gather_h_kernel<false, false, true><<<(NN + 7) / 8, gblk>>>(
        OFF_T1H, nullptr, 0, OFF_T2H,
        OFF_OFFN, OFF_DEGN, OFF_NE, OFF_DINV, nullptr, NN);
    // hh = elu(t2h @ W1 + b1)   fp16 out
    {
        dim3 grid(HIDC / 128, (NN + 127) / 128);
        gemm_mma_kernel<F_IN, HIDC, true, true><<<grid, 256>>>(
            OFF_T2H, OFF_WT1, OFF_HH, b1, NN);
    }

    // ---- Layer 2 ----
    // x2h = hh @ W2   fp16 out
    {
        dim3 grid(F_OUT / 128, (NN + 127) / 128);
        gemm_mma_kernel<HIDC, F_OUT, false, false><<<grid, 256>>>(
            OFF_HH, OFF_WT2, OFF_X2H, nullptr, NN);
    }
    // e_out[m] (fp32, returned) + eh[m] (fp16 copy)
    gather_h_kernel<false, true, true><<<(MM + 7) / 8, gblk>>>(
        OFF_X2H, e_out, 0, OFF_EH,
        OFF_OFFM, OFF_DEGM, OFF_EN, OFF_BINV, nullptr, MM);
    // out[n] = Dinv[n] * sum eh[m] + b2
    gather_h_kernel<true, true, false><<<(NN + 7) / 8, gblk>>>(
        OFF_EH, out, 0, 0,
        OFF_OFFN, OFF_DEGN, OFF_NE, OFF_DINV, b2, NN);
}